// round 5
// baseline (speedup 1.0000x reference)
#include <cuda_runtime.h>

// plane_rotations: the reference scan rebuilds the matrix from ZEROS each step
// (only rows i,j are written), so after step (1,2) the matrix is identically 0
// (exact in fp32) and out = x @ 0^T = 0 exactly. Pure zero-fill of d_out.
//
// History: R1 (float4), R2 (__stcs x4), R4 (L2-pinning split) all ~20.5-20.8us
// kernel / 6.45 TB/s, DRAM stuck at ~46%. Cyclic-thrash model falsified.
// New model: write-allocate costs LTS 2x (allocate + dirty writeback readout);
// LTS cap ~6300 B/cyc path-independent => user-visible ~5.8-6.5 TB/s. R5 test:
// write-through stores (STG.WT) leave no dirty line => 1x LTS traffic.
// Predict kernel ~12-14us if model right; neutral if HBM-write floor.

__global__ void __launch_bounds__(256) zero_fill_wt(float4* __restrict__ out,
                                                    long long n4) {
    const float4 z = make_float4(0.f, 0.f, 0.f, 0.f);
    long long stride = (long long)gridDim.x * blockDim.x;
    for (long long i = (long long)blockIdx.x * blockDim.x + threadIdx.x;
         i < n4; i += stride) {
        __stwt(&out[i], z);
    }
}

extern "C" void kernel_launch(void* const* d_in, const int* in_sizes, int n_in,
                              void* d_out, int out_size) {
    (void)d_in; (void)in_sizes; (void)n_in;
    long long n4 = (long long)out_size / 4;
    int threads = 256;
    int blocks = 148 * 16;
    long long needed = (n4 + threads - 1) / threads;
    if ((long long)blocks > needed) blocks = (int)needed;
    if (blocks < 1) blocks = 1;
    zero_fill_wt<<<blocks, threads>>>((float4*)d_out, n4);

    long long tail = (long long)out_size - n4 * 4;
    if (tail > 0) {
        cudaMemsetAsync((char*)d_out + n4 * 16, 0, tail * sizeof(float));
    }
}

// round 6
// speedup vs baseline: 1.0286x; 1.0286x over previous
#include <cuda_runtime.h>
#include <cstdint>

// plane_rotations: the reference scan rebuilds the matrix from ZEROS each step
// (only rows i,j are set), so after step (1,2) the matrix is identically 0
// (exact in fp32) and out = x @ 0^T = 0 exactly. Pure zero-fill of d_out.
//
// R1-R5: every store flavor (default/.cs/split/.wt/memset) = 20.5-20.9us
// in-window (6.45 TB/s, ~LTS cap) and dur floor 23.0us (= 134MB / 5.8TB/s
// DRAM drain). R6 hypothesis: the dur floor is recurring dirty-writeback of
// the 128MB output through the 126MB L2 every replay. Kill it by PINNING a
// 96MiB resident region with createpolicy L2::evict_last (lines re-dirtied in
// place, ~never written to DRAM) and streaming the rest with evict_first.

__global__ void __launch_bounds__(256) zero_fill_pinned(float4* __restrict__ out,
                                                        long long n4,
                                                        long long res4) {
    uint64_t pol_last, pol_first;
    asm volatile("createpolicy.fractional.L2::evict_last.b64 %0, 1.0;"
                 : "=l"(pol_last));
    asm volatile("createpolicy.fractional.L2::evict_first.b64 %0, 1.0;"
                 : "=l"(pol_first));

    long long stride = (long long)gridDim.x * blockDim.x;
    long long i = (long long)blockIdx.x * blockDim.x + threadIdx.x;

    // Resident region: evict_last -> pinned dirty in L2 across graph replays.
    for (; i < res4; i += stride) {
        asm volatile(
            "st.global.L2::cache_hint.v4.f32 [%0], {%1, %2, %3, %4}, %5;"
            :: "l"(out + i), "f"(0.f), "f"(0.f), "f"(0.f), "f"(0.f),
               "l"(pol_last)
            : "memory");
    }
    // Streaming region: evict_first -> designated victims, minimal pollution.
    for (; i < n4; i += stride) {
        asm volatile(
            "st.global.L2::cache_hint.v4.f32 [%0], {%1, %2, %3, %4}, %5;"
            :: "l"(out + i), "f"(0.f), "f"(0.f), "f"(0.f), "f"(0.f),
               "l"(pol_first)
            : "memory");
    }
}

extern "C" void kernel_launch(void* const* d_in, const int* in_sizes, int n_in,
                              void* d_out, int out_size) {
    (void)d_in; (void)in_sizes; (void)n_in;
    long long n4 = (long long)out_size / 4;
    // Pin 96 MiB of the 128 MiB output (~76% of the ~126MB L2, headroom for
    // streaming lines in flight and LTS hash imbalance).
    long long res4 = (96LL * 1024 * 1024) / 16;
    if (res4 > n4) res4 = n4;

    int threads = 256;
    int blocks = 148 * 16;
    long long needed = (n4 + threads - 1) / threads;
    if ((long long)blocks > needed) blocks = (int)needed;
    if (blocks < 1) blocks = 1;

    zero_fill_pinned<<<blocks, threads>>>((float4*)d_out, n4, res4);

    long long tail = (long long)out_size - n4 * 4;
    if (tail > 0) {
        cudaMemsetAsync((char*)d_out + n4 * 16, 0, tail * sizeof(float));
    }
}

// round 7
// speedup vs baseline: 1.1001x; 1.0695x over previous
#include <cuda_runtime.h>

// plane_rotations — FINAL (floor reached).
//
// Math: the reference's scan rebuilds the matrix from ZEROS each step (only
// rows i,j are written). The nonzero-row support collapses: I -> {0,k} chains
// -> step (1,2) reads two all-zero rows -> the matrix is identically 0
// (exact in fp32: c*0 - s*0 = 0) and stays 0 for all remaining steps. Hence
// out = x @ 0^T = 0 exactly, independent of inputs. The problem reduces to
// zero-filling the 128 MiB output.
//
// Measured floor: six mechanistically distinct write paths (default STG.128,
// STG.CS, L2-pin split, STG.WT, createpolicy evict_last/evict_first, driver
// memset) all execute in 20.3-20.9us = 6.45 TB/s user stores — the
// path-independent LTS store cap (~6300 B/cyc, B300_MICROARCH). evict_last
// DID cut DRAM traffic (45->41%) without changing runtime, confirming LTS
// (not HBM writeback) is binding. The graph memset node additionally replays
// ~1.7us cheaper than any kernel node, giving the best end-to-end time
// (23.0us). This is the optimum for this problem.

extern "C" void kernel_launch(void* const* d_in, const int* in_sizes, int n_in,
                              void* d_out, int out_size) {
    (void)d_in; (void)in_sizes; (void)n_in;
    cudaMemsetAsync(d_out, 0, (size_t)out_size * sizeof(float));
}